// round 5
// baseline (speedup 1.0000x reference)
#include <cuda_runtime.h>
#include <cuda_fp16.h>
#include <math.h>
#include <stdint.h>

#define BSZ 4
#define NX 8192
#define NY 1024
#define KNN 20
#define CD 24
#define HD 128
#define NB 5
#define NROWS (BSZ*NX*KNN)   /* 655360 */
#define NPTS  (BSZ*NX)       /* 32768  */
#define BN_EPS 1e-5f

typedef unsigned long long ull;

/* ---------------- f32x2 packed helpers ---------------- */
__device__ __forceinline__ ull ffma2(ull a, ull b, ull c) {
    ull d;
    asm("fma.rn.f32x2 %0, %1, %2, %3;" : "=l"(d) : "l"(a), "l"(b), "l"(c));
    return d;
}
__device__ __forceinline__ ull pack2(float lo, float hi) {
    ull d;
    asm("mov.b64 %0, {%1, %2};" : "=l"(d) : "f"(lo), "f"(hi));
    return d;
}
__device__ __forceinline__ float2 unpack2(ull v) {
    float2 r;
    asm("mov.b64 {%0, %1}, %2;" : "=f"(r.x), "=f"(r.y) : "l"(v));
    return r;
}

/* ---------------- scratch ---------------- */
__device__ int    g_idx[NROWS];                 /* 2.6 MB */
__device__ float  g_U[BSZ*NY*HD];               /* 2 MB   */
__device__ float  g_V[BSZ*NX*HD];               /* 16 MB  */
__device__ __half g_h2h[(size_t)NROWS*HD];      /* 168 MB */
__device__ float  g_pmax[NPTS*CD];              /* 3 MB   */
__device__ float  g_pmin[NPTS*CD];              /* 3 MB   */
__device__ float  g_sum[3*HD];
__device__ float  g_sumsq[3*HD];
__device__ float  g_scale[3*HD];
__device__ float  g_shift[3*HD];
__device__ int    g_cnt[3];

__device__ __forceinline__ void bn_finalize(int L, int C, float invN,
                                            const float* g, const float* b, int c) {
    if (c < C) {
        float mean = g_sum[L*HD + c] * invN;
        float var  = g_sumsq[L*HD + c] * invN - mean*mean;
        float sc = g[c] * rsqrtf(var + BN_EPS);
        g_scale[L*HD + c] = sc;
        g_shift[L*HD + c] = b[c] - mean*sc;
    }
}

/* ---------------- K1: KNN (+ zero stats/counters in block 0) ---------------- */
__global__ void k_knn(const float* __restrict__ p, const float* __restrict__ pc) {
    __shared__ float qx[NY], qy[NY], qz[NY], qn[NY];
    int b = blockIdx.y;
    int t = threadIdx.x;
    if (blockIdx.x == 0 && blockIdx.y == 0) {
        /* FIX: 256 threads must cover all 3*HD=384 entries — stride the loop */
        for (int c = t; c < 3*HD; c += 256) { g_sum[c] = 0.f; g_sumsq[c] = 0.f; }
        if (t < 3) g_cnt[t] = 0;
    }
    for (int j = t; j < NY; j += blockDim.x) {
        float x = pc[(b*NY + j)*3 + 0];
        float y = pc[(b*NY + j)*3 + 1];
        float z = pc[(b*NY + j)*3 + 2];
        qx[j] = x; qy[j] = y; qz[j] = z;
        qn[j] = x*x + y*y + z*z;
    }
    __syncthreads();

    int n = blockIdx.x * blockDim.x + t;
    float px = p[(b*NX + n)*3 + 0];
    float py = p[(b*NX + n)*3 + 1];
    float pz = p[(b*NX + n)*3 + 2];
    float pn = px*px + py*py + pz*pz;

    float bd[KNN]; int bi[KNN];
#pragma unroll
    for (int s = 0; s < KNN; s++) { bd[s] = 3.4e38f; bi[s] = 0; }
    float worst = 3.4e38f; int wpos = 0;

    for (int j = 0; j < NY; j++) {
        float d = pn + qn[j] - 2.f*(px*qx[j] + py*qy[j] + pz*qz[j]);
        if (d < worst) {
#pragma unroll
            for (int s = 0; s < KNN; s++) if (s == wpos) { bd[s] = d; bi[s] = j; }
            worst = bd[0]; wpos = 0;
#pragma unroll
            for (int s = 1; s < KNN; s++) if (bd[s] > worst) { worst = bd[s]; wpos = s; }
        }
    }
    int base = (b*NX + n)*KNN;
#pragma unroll
    for (int s = 0; s < KNN; s++) g_idx[base + s] = bi[s];
}

/* ---------------- K2: fused preU + preV ---------------- */
/* blocks [0,128): U (32 rows each).  blocks [128,640): V (64 rows each). */
__global__ void k_preUV(const float* __restrict__ p, const float* __restrict__ pc,
                        const float* __restrict__ feat, const float* __restrict__ w1) {
    int t = threadIdx.x;
    if (blockIdx.x < 128) {
        __shared__ float in_s[32][28];
        int base = blockIdx.x * 32;
        for (int e = t; e < 32*27; e += 128) {
            int r = e / 27, k = e % 27;
            int row = base + r;
            in_s[r][k] = (k < 3) ? pc[row*3 + k] : feat[row*24 + (k - 3)];
        }
        __syncthreads();
        float wr[27];
#pragma unroll
        for (int d = 0; d < 3; d++)  wr[d]     = w1[d*HD + t];
#pragma unroll
        for (int k = 0; k < 24; k++) wr[3 + k] = w1[(6 + k)*HD + t];
        for (int r = 0; r < 32; r++) {
            float acc = 0.f;
#pragma unroll
            for (int k = 0; k < 27; k++) acc = fmaf(in_s[r][k], wr[k], acc);
            g_U[(base + r)*HD + t] = acc;
        }
    } else {
        __shared__ float ps[64][4];
        int base = (blockIdx.x - 128) * 64;
        for (int e = t; e < 64*3; e += 128) {
            int r = e / 3, d = e % 3;
            ps[r][d] = p[(base + r)*3 + d];
        }
        __syncthreads();
        float wd0 = w1[3*HD + t] - w1[0*HD + t];
        float wd1 = w1[4*HD + t] - w1[1*HD + t];
        float wd2 = w1[5*HD + t] - w1[2*HD + t];
        for (int r = 0; r < 64; r++) {
            float v = fmaf(ps[r][0], wd0, fmaf(ps[r][1], wd1, ps[r][2]*wd2));
            g_V[(base + r)*HD + t] = v;
        }
    }
}

/* ---------------- K3: stats of h1 + fused finalize layer 0 ---------------- */
__global__ void k_stats1(const float* __restrict__ bn1g, const float* __restrict__ bn1b,
                         float invN) {
    __shared__ int uo[512], vo[512];
    __shared__ int lastflag;
    int blk = blockIdx.x, t = threadIdx.x;
    int base = blk * 512;
    for (int r = t; r < 512; r += 256) {
        int grow = base + r;
        int j = g_idx[grow];
        int b = grow / (NX*KNN);
        int n = (grow / KNN) % NX;
        uo[r] = (b*NY + j)*HD;
        vo[r] = (b*NX + n)*HD;
    }
    __syncthreads();
    int c = t & 127, rg = t >> 7;
    float s = 0.f, s2 = 0.f;
    for (int r = rg; r < 512; r += 2) {
        float v = g_U[uo[r] + c] + g_V[vo[r] + c];
        s += v; s2 += v*v;
    }
    atomicAdd(&g_sum[c], s);
    atomicAdd(&g_sumsq[c], s2);
    __threadfence();
    if (t == 0) lastflag = (atomicAdd(&g_cnt[0], 1) == (int)gridDim.x - 1);
    __syncthreads();
    if (lastflag) bn_finalize(0, 128, invN, bn1g, bn1b, t);
}

/* ---------------- K4: conv2 GEMM (f32x2) + stats2 + finalize layer 1 -------- */
__global__ void __launch_bounds__(256) k_conv2(const float* __restrict__ w2,
                                               const float* __restrict__ bn2g,
                                               const float* __restrict__ bn2b,
                                               float invN) {
    extern __shared__ char smemraw[];
    float* a_s = (float*)smemraw;                    /* 64*128 f = 32KB  */
    ull*   wp  = (ull*)(a_s + 64*128);               /* 64*128 u64 = 64KB*/
    float* sc  = (float*)(wp + 64*128);              /* 128 */
    float* sh  = sc + 128;                           /* 128 */
    int*   uo  = (int*)(sh + 128);                   /* 64  */
    int*   vo  = uo + 64;                            /* 64  */
    __shared__ int lastflag;

    int t = threadIdx.x, blk = blockIdx.x;
    int rbase = blk * 64;
    if (t < 64) {
        int grow = rbase + t;
        int j = g_idx[grow];
        int b = grow / (NX*KNN);
        int n = (grow / KNN) % NX;
        uo[t] = (b*NY + j)*HD;
        vo[t] = (b*NX + n)*HD;
    }
    if (t < 128) { sc[t] = g_scale[t]; sh[t] = g_shift[t]; }
    /* pre-pack weights into k-pairs: wp[p*128+col] = (w2[2p][col], w2[2p+1][col]) */
    for (int e = t; e < 64*128; e += 256) {
        int pp = e >> 7, col = e & 127;
        wp[e] = pack2(__ldg(&w2[(2*pp)*128 + col]), __ldg(&w2[(2*pp+1)*128 + col]));
    }
    __syncthreads();

    {   /* stage A tile: h1 = U+V, then bn1 + lrelu */
        int k = t & 127, r0 = t >> 7;
        for (int r = r0; r < 64; r += 2) {
            float v = g_U[uo[r] + k] + g_V[vo[r] + k];
            v = fmaf(sc[k], v, sh[k]);
            v = (v > 0.f) ? v : 0.2f*v;
            a_s[r*128 + k] = v;
        }
    }
    __syncthreads();

    int col = t & 127, rg = t >> 7;
    ull acc2[32];
#pragma unroll
    for (int r = 0; r < 32; r++) acc2[r] = 0ULL;
    const float* ar = a_s + (rg*32)*128;

    for (int kp = 0; kp < 64; kp += 2) {
        ull w0 = wp[kp*128 + col];
        ull w1 = wp[(kp+1)*128 + col];
#pragma unroll
        for (int r = 0; r < 32; r++) {
            ulonglong2 av = *(const ulonglong2*)&ar[r*128 + 2*kp];
            acc2[r] = ffma2(av.x, w0, acc2[r]);
            acc2[r] = ffma2(av.y, w1, acc2[r]);
        }
    }
    __syncthreads();                 /* done reading a_s */
    __half* hst = (__half*)a_s;      /* 64*128 halfs = 16KB */
    float s = 0.f, s2 = 0.f;
#pragma unroll
    for (int r = 0; r < 32; r++) {
        float2 f = unpack2(acc2[r]);
        float v = f.x + f.y;
        hst[(rg*32 + r)*128 + col] = __float2half(v);
        s += v; s2 += v*v;
    }
    atomicAdd(&g_sum[HD + col], s);
    atomicAdd(&g_sumsq[HD + col], s2);
    __syncthreads();
    /* coalesced fp16 tile store: 64 rows x 256B */
    {
        uint4* dst = (uint4*)&g_h2h[(size_t)rbase*HD];
        const uint4* src = (const uint4*)hst;
        for (int e = t; e < 1024; e += 256) dst[e] = src[e];
    }
    __threadfence();
    if (t == 0) lastflag = (atomicAdd(&g_cnt[1], 1) == (int)gridDim.x - 1);
    __syncthreads();
    if (lastflag) bn_finalize(1, 128, invN, bn2g, bn2b, t);
}

/* ---------------- K5: conv3 GEMM (f32x2) + fused pool + finalize layer 2 ---- */
/* tile: 160 rows = exactly 8 points, 24 cols, 192 threads */
__global__ void __launch_bounds__(192) k_conv3p(const float* __restrict__ w3,
                                                const float* __restrict__ bn3g,
                                                const float* __restrict__ bn3b,
                                                float invN) {
    extern __shared__ char smemraw[];
    float* a_s = (float*)smemraw;          /* 160*130 (pad, 8B-aligned rows) */
    ull*   wp  = (ull*)(a_s + 160*130);    /* 64*24 u64 = 12KB */
    float* sc  = (float*)(wp + 64*24);     /* 128 */
    float* sh  = sc + 128;                 /* 128 */
    float* red = sh + 128;                 /* 48  */
    __shared__ int lastflag;

    int t = threadIdx.x, blk = blockIdx.x;
    int rbase = blk * 160;
    for (int e = t; e < 64*24; e += 192) {
        int pp = e / 24, col = e % 24;
        wp[e] = pack2(__ldg(&w3[(2*pp)*24 + col]), __ldg(&w3[(2*pp+1)*24 + col]));
    }
    if (t < 128) { sc[t] = g_scale[HD + t]; sh[t] = g_shift[HD + t]; }
    if (t < 48)  red[t] = 0.f;
    __syncthreads();

    const __half2* hp = (const __half2*)g_h2h + (size_t)rbase*64;
    for (int e = t; e < 160*64; e += 192) {
        int r = e >> 6, kp = e & 63;
        float2 f = __half22float2(hp[(size_t)r*64 + kp]);
        int k0 = 2*kp;
        float v0 = fmaf(sc[k0],   f.x, sh[k0]);   v0 = (v0 > 0.f) ? v0 : 0.2f*v0;
        float v1 = fmaf(sc[k0+1], f.y, sh[k0+1]); v1 = (v1 > 0.f) ? v1 : 0.2f*v1;
        a_s[r*130 + k0]     = v0;
        a_s[r*130 + k0 + 1] = v1;
    }
    __syncthreads();

    int col = t % 24, rg = t / 24;   /* rg 0..7, rows r*8+rg */
    ull acc2[20];
#pragma unroll
    for (int r = 0; r < 20; r++) acc2[r] = 0ULL;
#pragma unroll 2
    for (int p = 0; p < 64; p++) {
        ull wv = wp[p*24 + col];
#pragma unroll
        for (int r = 0; r < 20; r++) {
            ull a = *(const ull*)&a_s[(r*8 + rg)*130 + 2*p];
            acc2[r] = ffma2(a, wv, acc2[r]);
        }
    }
    __syncthreads();                 /* a_s now reusable */
    float* h3s = a_s;                /* 160*24 */
    float s = 0.f, s2 = 0.f;
#pragma unroll
    for (int r = 0; r < 20; r++) {
        float2 f = unpack2(acc2[r]);
        float v = f.x + f.y;
        h3s[(r*8 + rg)*24 + col] = v;
        s += v; s2 += v*v;
    }
    atomicAdd(&red[col], s);
    atomicAdd(&red[24 + col], s2);
    __syncthreads();

    {   /* fused pool: 8 points x 24 cols == 192 threads */
        int pl = t / 24, c2 = t % 24;
        float mx = -3.4e38f, mn = 3.4e38f;
#pragma unroll
        for (int kk = 0; kk < KNN; kk++) {
            float v = h3s[(pl*KNN + kk)*24 + c2];
            mx = fmaxf(mx, v); mn = fminf(mn, v);
        }
        int pt = blk*8 + pl;
        g_pmax[pt*24 + c2] = mx;
        g_pmin[pt*24 + c2] = mn;
    }
    if (t < 24) {
        atomicAdd(&g_sum[2*HD + t],   red[t]);
        atomicAdd(&g_sumsq[2*HD + t], red[24 + t]);
    }
    __threadfence();
    if (t == 0) lastflag = (atomicAdd(&g_cnt[2], 1) == (int)gridDim.x - 1);
    __syncthreads();
    if (lastflag) bn_finalize(2, 24, invN, bn3g, bn3b, t);
}

/* ---------------- K6: ResNet-FC head (f32x2, bn3+pool-select on load) ------- */
/* block = 64 points, 256 threads = 32 colgroups(x4) x 8 rowgroups(x8) */
__global__ void __launch_bounds__(256) k_head(const float* __restrict__ p,
                       const float* __restrict__ fpw, const float* __restrict__ fpb,
                       const float* __restrict__ fcw, const float* __restrict__ fcb,
                       const float* __restrict__ b0w, const float* __restrict__ b0b,
                       const float* __restrict__ b1w, const float* __restrict__ b1b,
                       const float* __restrict__ fow, const float* __restrict__ fob,
                       float* __restrict__ out) {
    extern __shared__ char smemraw[];
    float* net  = (float*)smemraw;     /* 64*128 */
    float* rnet = net  + 64*128;       /* 64*128 */
    float* rhh  = rnet + 64*128;       /* 64*128 */
    float* cb   = rhh  + 64*128;       /* 64*24  */
    float* pb   = cb   + 64*24;        /* 192    */
    float* fo   = pb   + 192;          /* 128    */

    int t = threadIdx.x;
    int base = blockIdx.x * 64;
    for (int e = t; e < 64*CD; e += 256) {
        int c2 = e % 24;
        float scv = g_scale[2*HD + c2], shv = g_shift[2*HD + c2];
        float v = (scv >= 0.f) ? g_pmax[base*24 + e] : g_pmin[base*24 + e];
        v = fmaf(scv, v, shv);
        cb[e] = (v > 0.f) ? v : 0.2f*v;
    }
    if (t < 192) pb[t] = p[base*3 + t];
    if (t < 128) fo[t] = fow[t];
    __syncthreads();

    int cg  = (t & 31) * 4;     /* col start */
    int row0 = (t >> 5) * 8;    /* row start */

    { /* net = p @ fc_p_w + b */
        float4 w0 = *(const float4*)&fpw[0*HD + cg];
        float4 w1 = *(const float4*)&fpw[1*HD + cg];
        float4 w2 = *(const float4*)&fpw[2*HD + cg];
        float4 b4 = *(const float4*)&fpb[cg];
#pragma unroll
        for (int rr = 0; rr < 8; rr++) {
            int row = row0 + rr;
            float p0 = pb[row*3+0], p1 = pb[row*3+1], p2 = pb[row*3+2];
            float4 v;
            v.x = fmaf(p0,w0.x, fmaf(p1,w1.x, fmaf(p2,w2.x, b4.x)));
            v.y = fmaf(p0,w0.y, fmaf(p1,w1.y, fmaf(p2,w2.y, b4.y)));
            v.z = fmaf(p0,w0.z, fmaf(p1,w1.z, fmaf(p2,w2.z, b4.z)));
            v.w = fmaf(p0,w0.w, fmaf(p1,w1.w, fmaf(p2,w2.w, b4.w)));
            *(float4*)&net[row*128 + cg] = v;
        }
    }
    __syncthreads();

    for (int i = 0; i < NB; i++) {
        { /* net += c @ fc_c[i] + b ; rnet = relu(net) */
            float4 b4 = *(const float4*)&fcb[i*HD + cg];
            ull acc2[8][4];
#pragma unroll
            for (int rr = 0; rr < 8; rr++) {
                float4 v = *(const float4*)&net[(row0+rr)*128 + cg];
                acc2[rr][0] = pack2(v.x + b4.x, 0.f);
                acc2[rr][1] = pack2(v.y + b4.y, 0.f);
                acc2[rr][2] = pack2(v.z + b4.z, 0.f);
                acc2[rr][3] = pack2(v.w + b4.w, 0.f);
            }
#pragma unroll 2
            for (int k = 0; k < CD; k += 2) {
                float4 wa = __ldg((const float4*)&fcw[(i*CD + k)*HD + cg]);
                float4 wb = __ldg((const float4*)&fcw[(i*CD + k + 1)*HD + cg]);
                ull wx = pack2(wa.x, wb.x), wy = pack2(wa.y, wb.y);
                ull wz = pack2(wa.z, wb.z), ww = pack2(wa.w, wb.w);
#pragma unroll
                for (int rr = 0; rr < 8; rr++) {
                    ull a = *(const ull*)&cb[(row0+rr)*24 + k];
                    acc2[rr][0] = ffma2(a, wx, acc2[rr][0]);
                    acc2[rr][1] = ffma2(a, wy, acc2[rr][1]);
                    acc2[rr][2] = ffma2(a, wz, acc2[rr][2]);
                    acc2[rr][3] = ffma2(a, ww, acc2[rr][3]);
                }
            }
#pragma unroll
            for (int rr = 0; rr < 8; rr++) {
                int row = row0 + rr;
                float2 f0 = unpack2(acc2[rr][0]), f1 = unpack2(acc2[rr][1]);
                float2 f2 = unpack2(acc2[rr][2]), f3 = unpack2(acc2[rr][3]);
                float4 v; v.x = f0.x+f0.y; v.y = f1.x+f1.y; v.z = f2.x+f2.y; v.w = f3.x+f3.y;
                *(float4*)&net[row*128 + cg] = v;
                float4 rv;
                rv.x = fmaxf(v.x, 0.f); rv.y = fmaxf(v.y, 0.f);
                rv.z = fmaxf(v.z, 0.f); rv.w = fmaxf(v.w, 0.f);
                *(float4*)&rnet[row*128 + cg] = rv;
            }
        }
        __syncthreads();
        { /* rhh = relu( rnet @ blk0[i] + b ) */
            float4 b4 = *(const float4*)&b0b[i*HD + cg];
            ull acc2[8][4];
#pragma unroll
            for (int rr = 0; rr < 8; rr++) {
                acc2[rr][0] = pack2(b4.x, 0.f); acc2[rr][1] = pack2(b4.y, 0.f);
                acc2[rr][2] = pack2(b4.z, 0.f); acc2[rr][3] = pack2(b4.w, 0.f);
            }
            const float* wbase = b0w + (size_t)i*HD*HD;
#pragma unroll 2
            for (int k = 0; k < HD; k += 2) {
                float4 wa = __ldg((const float4*)&wbase[k*HD + cg]);
                float4 wb = __ldg((const float4*)&wbase[(k+1)*HD + cg]);
                ull wx = pack2(wa.x, wb.x), wy = pack2(wa.y, wb.y);
                ull wz = pack2(wa.z, wb.z), ww = pack2(wa.w, wb.w);
#pragma unroll
                for (int rr = 0; rr < 8; rr++) {
                    ull a = *(const ull*)&rnet[(row0+rr)*128 + k];
                    acc2[rr][0] = ffma2(a, wx, acc2[rr][0]);
                    acc2[rr][1] = ffma2(a, wy, acc2[rr][1]);
                    acc2[rr][2] = ffma2(a, wz, acc2[rr][2]);
                    acc2[rr][3] = ffma2(a, ww, acc2[rr][3]);
                }
            }
#pragma unroll
            for (int rr = 0; rr < 8; rr++) {
                float2 f0 = unpack2(acc2[rr][0]), f1 = unpack2(acc2[rr][1]);
                float2 f2 = unpack2(acc2[rr][2]), f3 = unpack2(acc2[rr][3]);
                float4 rv;
                rv.x = fmaxf(f0.x+f0.y, 0.f); rv.y = fmaxf(f1.x+f1.y, 0.f);
                rv.z = fmaxf(f2.x+f2.y, 0.f); rv.w = fmaxf(f3.x+f3.y, 0.f);
                *(float4*)&rhh[(row0+rr)*128 + cg] = rv;
            }
        }
        __syncthreads();
        { /* net += rhh @ blk1[i] + b */
            float4 b4 = *(const float4*)&b1b[i*HD + cg];
            ull acc2[8][4];
#pragma unroll
            for (int rr = 0; rr < 8; rr++) {
                acc2[rr][0] = pack2(b4.x, 0.f); acc2[rr][1] = pack2(b4.y, 0.f);
                acc2[rr][2] = pack2(b4.z, 0.f); acc2[rr][3] = pack2(b4.w, 0.f);
            }
            const float* wbase = b1w + (size_t)i*HD*HD;
#pragma unroll 2
            for (int k = 0; k < HD; k += 2) {
                float4 wa = __ldg((const float4*)&wbase[k*HD + cg]);
                float4 wb = __ldg((const float4*)&wbase[(k+1)*HD + cg]);
                ull wx = pack2(wa.x, wb.x), wy = pack2(wa.y, wb.y);
                ull wz = pack2(wa.z, wb.z), ww = pack2(wa.w, wb.w);
#pragma unroll
                for (int rr = 0; rr < 8; rr++) {
                    ull a = *(const ull*)&rhh[(row0+rr)*128 + k];
                    acc2[rr][0] = ffma2(a, wx, acc2[rr][0]);
                    acc2[rr][1] = ffma2(a, wy, acc2[rr][1]);
                    acc2[rr][2] = ffma2(a, wz, acc2[rr][2]);
                    acc2[rr][3] = ffma2(a, ww, acc2[rr][3]);
                }
            }
#pragma unroll
            for (int rr = 0; rr < 8; rr++) {
                int row = row0 + rr;
                float2 f0 = unpack2(acc2[rr][0]), f1 = unpack2(acc2[rr][1]);
                float2 f2 = unpack2(acc2[rr][2]), f3 = unpack2(acc2[rr][3]);
                float4 v = *(const float4*)&net[row*128 + cg];
                v.x += f0.x+f0.y; v.y += f1.x+f1.y;
                v.z += f2.x+f2.y; v.w += f3.x+f3.y;
                *(float4*)&net[row*128 + cg] = v;
            }
        }
        __syncthreads();
    }

    if (t < 64) {
        float s = fob[0];
        for (int c2 = 0; c2 < HD; c2++)
            s = fmaf(fmaxf(net[t*128 + c2], 0.f), fo[c2], s);
        out[base + t] = s;
    }
}

/* ---------------- launch ---------------- */
extern "C" void kernel_launch(void* const* d_in, const int* in_sizes, int n_in,
                              void* d_out, int out_size) {
    (void)in_sizes; (void)n_in; (void)out_size;
    const float* p     = (const float*)d_in[0];
    const float* pc    = (const float*)d_in[1];
    const float* feat  = (const float*)d_in[2];
    const float* w1    = (const float*)d_in[3];
    const float* bn1g  = (const float*)d_in[4];
    const float* bn1b  = (const float*)d_in[5];
    const float* w2    = (const float*)d_in[6];
    const float* bn2g  = (const float*)d_in[7];
    const float* bn2b  = (const float*)d_in[8];
    const float* w3    = (const float*)d_in[9];
    const float* bn3g  = (const float*)d_in[10];
    const float* bn3b  = (const float*)d_in[11];
    const float* fpw   = (const float*)d_in[12];
    const float* fpb   = (const float*)d_in[13];
    const float* fcw   = (const float*)d_in[14];
    const float* fcb   = (const float*)d_in[15];
    const float* b0w   = (const float*)d_in[16];
    const float* b0b   = (const float*)d_in[17];
    const float* b1w   = (const float*)d_in[18];
    const float* b1b   = (const float*)d_in[19];
    const float* fow   = (const float*)d_in[20];
    const float* fob   = (const float*)d_in[21];
    float* out = (float*)d_out;

    const int SMEM2 = 64*128*4 + 64*128*8 + 2*128*4 + 2*64*4;         /* ~99.8 KB */
    const int SMEM3 = 160*130*4 + 64*24*8 + 2*128*4 + 48*4;           /* ~96.7 KB */
    const int SMEMH = (3*64*128 + 64*24 + 192 + 128) * 4;             /* ~105.7 KB*/
    cudaFuncSetAttribute(k_conv2,  cudaFuncAttributeMaxDynamicSharedMemorySize, SMEM2);
    cudaFuncSetAttribute(k_conv3p, cudaFuncAttributeMaxDynamicSharedMemorySize, SMEM3);
    cudaFuncSetAttribute(k_head,   cudaFuncAttributeMaxDynamicSharedMemorySize, SMEMH);

    float invN = 1.0f / (float)NROWS;

    k_knn<<<dim3(NX/256, BSZ), 256>>>(p, pc);
    k_preUV<<<128 + NPTS/64, 128>>>(p, pc, feat, w1);
    k_stats1<<<NROWS/512, 256>>>(bn1g, bn1b, invN);
    k_conv2<<<NROWS/64, 256, SMEM2>>>(w2, bn2g, bn2b, invN);
    k_conv3p<<<NROWS/160, 192, SMEM3>>>(w3, bn3g, bn3b, invN);
    k_head<<<NPTS/64, 256, SMEMH>>>(p, fpw, fpb, fcw, fcb,
                                    b0w, b0b, b1w, b1b, fow, fob, out);
}

// round 8
// speedup vs baseline: 1.3890x; 1.3890x over previous
#include <cuda_runtime.h>
#include <cuda_fp16.h>
#include <math.h>
#include <stdint.h>

#define BSZ 4
#define NX 8192
#define NY 1024
#define KNN 20
#define CD 24
#define HD 128
#define NB 5
#define NROWS (BSZ*NX*KNN)   /* 655360 */
#define NPTS  (BSZ*NX)       /* 32768  */
#define BN_EPS 1e-5f

typedef unsigned long long ull;

/* ---------------- f32x2 packed helpers (conv3/head) ---------------- */
__device__ __forceinline__ ull ffma2(ull a, ull b, ull c) {
    ull d;
    asm("fma.rn.f32x2 %0, %1, %2, %3;" : "=l"(d) : "l"(a), "l"(b), "l"(c));
    return d;
}
__device__ __forceinline__ ull pack2(float lo, float hi) {
    ull d;
    asm("mov.b64 %0, {%1, %2};" : "=l"(d) : "f"(lo), "f"(hi));
    return d;
}
__device__ __forceinline__ float2 unpack2(ull v) {
    float2 r;
    asm("mov.b64 {%0, %1}, %2;" : "=f"(r.x), "=f"(r.y) : "l"(v));
    return r;
}

/* ---------------- warp mma m16n8k16 f16 -> f32 ---------------- */
__device__ __forceinline__ void mma16816(float* d, uint32_t a0, uint32_t a1,
                                         uint32_t a2, uint32_t a3,
                                         uint32_t b0, uint32_t b1) {
    asm volatile(
        "mma.sync.aligned.m16n8k16.row.col.f32.f16.f16.f32 "
        "{%0,%1,%2,%3}, {%4,%5,%6,%7}, {%8,%9}, {%0,%1,%2,%3};"
        : "+f"(d[0]), "+f"(d[1]), "+f"(d[2]), "+f"(d[3])
        : "r"(a0), "r"(a1), "r"(a2), "r"(a3), "r"(b0), "r"(b1));
}

/* ---------------- scratch ---------------- */
__device__ int    g_idx[NROWS];                 /* 2.6 MB */
__device__ float  g_U[BSZ*NY*HD];               /* 2 MB   */
__device__ float  g_V[BSZ*NX*HD];               /* 16 MB  */
__device__ __half g_h2h[(size_t)NROWS*HD];      /* 168 MB */
__device__ float  g_pmax[NPTS*CD];              /* 3 MB   */
__device__ float  g_pmin[NPTS*CD];              /* 3 MB   */
__device__ __half g_W16[HD*HD];                 /* w2^T fp16 */
__device__ float  g_sum[3*HD];
__device__ float  g_sumsq[3*HD];
__device__ float  g_scale[3*HD];
__device__ float  g_shift[3*HD];
__device__ int    g_cnt[3];

__device__ __forceinline__ void bn_finalize(int L, int C, float invN,
                                            const float* g, const float* b, int c) {
    if (c < C) {
        float mean = g_sum[L*HD + c] * invN;
        float var  = g_sumsq[L*HD + c] * invN - mean*mean;
        float sc = g[c] * rsqrtf(var + BN_EPS);
        g_scale[L*HD + c] = sc;
        g_shift[L*HD + c] = b[c] - mean*sc;
    }
}

/* ---------------- K1: KNN (+ zero stats/counters in block 0) ---------------- */
__global__ void k_knn(const float* __restrict__ p, const float* __restrict__ pc) {
    __shared__ float qx[NY], qy[NY], qz[NY], qn[NY];
    int b = blockIdx.y;
    int t = threadIdx.x;
    if (blockIdx.x == 0 && blockIdx.y == 0) {
        for (int c = t; c < 3*HD; c += 256) { g_sum[c] = 0.f; g_sumsq[c] = 0.f; }
        if (t < 3) g_cnt[t] = 0;
    }
    for (int j = t; j < NY; j += blockDim.x) {
        float x = pc[(b*NY + j)*3 + 0];
        float y = pc[(b*NY + j)*3 + 1];
        float z = pc[(b*NY + j)*3 + 2];
        qx[j] = x; qy[j] = y; qz[j] = z;
        qn[j] = x*x + y*y + z*z;
    }
    __syncthreads();

    int n = blockIdx.x * blockDim.x + t;
    float px = p[(b*NX + n)*3 + 0];
    float py = p[(b*NX + n)*3 + 1];
    float pz = p[(b*NX + n)*3 + 2];
    float pn = px*px + py*py + pz*pz;

    float bd[KNN]; int bi[KNN];
#pragma unroll
    for (int s = 0; s < KNN; s++) { bd[s] = 3.4e38f; bi[s] = 0; }
    float worst = 3.4e38f; int wpos = 0;

    for (int j = 0; j < NY; j++) {
        float d = pn + qn[j] - 2.f*(px*qx[j] + py*qy[j] + pz*qz[j]);
        if (d < worst) {
#pragma unroll
            for (int s = 0; s < KNN; s++) if (s == wpos) { bd[s] = d; bi[s] = j; }
            worst = bd[0]; wpos = 0;
#pragma unroll
            for (int s = 1; s < KNN; s++) if (bd[s] > worst) { worst = bd[s]; wpos = s; }
        }
    }
    int base = (b*NX + n)*KNN;
#pragma unroll
    for (int s = 0; s < KNN; s++) g_idx[base + s] = bi[s];
}

/* ---------------- K2: fused preU + preV ---------------- */
__global__ void k_preUV(const float* __restrict__ p, const float* __restrict__ pc,
                        const float* __restrict__ feat, const float* __restrict__ w1) {
    int t = threadIdx.x;
    if (blockIdx.x < 128) {
        __shared__ float in_s[32][28];
        int base = blockIdx.x * 32;
        for (int e = t; e < 32*27; e += 128) {
            int r = e / 27, k = e % 27;
            int row = base + r;
            in_s[r][k] = (k < 3) ? pc[row*3 + k] : feat[row*24 + (k - 3)];
        }
        __syncthreads();
        float wr[27];
#pragma unroll
        for (int d = 0; d < 3; d++)  wr[d]     = w1[d*HD + t];
#pragma unroll
        for (int k = 0; k < 24; k++) wr[3 + k] = w1[(6 + k)*HD + t];
        for (int r = 0; r < 32; r++) {
            float acc = 0.f;
#pragma unroll
            for (int k = 0; k < 27; k++) acc = fmaf(in_s[r][k], wr[k], acc);
            g_U[(base + r)*HD + t] = acc;
        }
    } else {
        __shared__ float ps[64][4];
        int base = (blockIdx.x - 128) * 64;
        for (int e = t; e < 64*3; e += 128) {
            int r = e / 3, d = e % 3;
            ps[r][d] = p[(base + r)*3 + d];
        }
        __syncthreads();
        float wd0 = w1[3*HD + t] - w1[0*HD + t];
        float wd1 = w1[4*HD + t] - w1[1*HD + t];
        float wd2 = w1[5*HD + t] - w1[2*HD + t];
        for (int r = 0; r < 64; r++) {
            float v = fmaf(ps[r][0], wd0, fmaf(ps[r][1], wd1, ps[r][2]*wd2));
            g_V[(base + r)*HD + t] = v;
        }
    }
}

/* ---------------- K2b: w2^T -> fp16 ---------------- */
__global__ void k_prepW(const float* __restrict__ w2) {
    int e = blockIdx.x * 256 + threadIdx.x;     /* 16384 */
    int n = e >> 7, k = e & 127;
    g_W16[e] = __float2half(w2[k*HD + n]);
}

/* ---------------- K3: stats of h1 + fused finalize layer 0 ---------------- */
__global__ void k_stats1(const float* __restrict__ bn1g, const float* __restrict__ bn1b,
                         float invN) {
    __shared__ int uo[512], vo[512];
    __shared__ int lastflag;
    int blk = blockIdx.x, t = threadIdx.x;
    int base = blk * 512;
    for (int r = t; r < 512; r += 256) {
        int grow = base + r;
        int j = g_idx[grow];
        int b = grow / (NX*KNN);
        int n = (grow / KNN) % NX;
        uo[r] = (b*NY + j)*HD;
        vo[r] = (b*NX + n)*HD;
    }
    __syncthreads();
    int c = t & 127, rg = t >> 7;
    float s = 0.f, s2 = 0.f;
    for (int r = rg; r < 512; r += 2) {
        float v = g_U[uo[r] + c] + g_V[vo[r] + c];
        s += v; s2 += v*v;
    }
    atomicAdd(&g_sum[c], s);
    atomicAdd(&g_sumsq[c], s2);
    __threadfence();
    if (t == 0) lastflag = (atomicAdd(&g_cnt[0], 1) == (int)gridDim.x - 1);
    __syncthreads();
    if (lastflag) bn_finalize(0, 128, invN, bn1g, bn1b, t);
}

/* ---------------- K4: conv2 via warp mma (fp16 in, fp32 acc) ----------------
   tile 128x128, K=128. 8 warps x 16 rows. A/B smem pitch 136 halfs (272B).   */
#define C2_PH 136          /* halfs per row */
#define C2_PW 68           /* u32/half2 per row */
#define C2_AS 2048
#define C2_BS (2048 + 34816)
#define C2_SMEM (2048 + 2*34816)
__global__ void __launch_bounds__(256) k_conv2(const float* __restrict__ bn2g,
                                               const float* __restrict__ bn2b,
                                               float invN) {
    extern __shared__ char smemraw[];
    float* sc = (float*)smemraw;
    float* sh = sc + 128;
    int*   uo = (int*)(sh + 128);
    int*   vo = uo + 128;
    __shared__ int lastflag;

    int t = threadIdx.x, blk = blockIdx.x;
    int lane = t & 31, wid = t >> 5;
    int rbase = blk * 128;
    __half* As = (__half*)(smemraw + C2_AS);
    __half* Bs = (__half*)(smemraw + C2_BS);

    if (t < 128) {
        int grow = rbase + t;
        int j = g_idx[grow];
        int b = grow / (NX*KNN);
        int n = (grow / KNN) % NX;
        uo[t] = (b*NY + j)*HD;
        vo[t] = (b*NX + n)*HD;
    } else {
        int c = t - 128;
        sc[c] = g_scale[c];
        sh[c] = g_shift[c];
    }
    __syncthreads();

    /* stage B (w2^T fp16, coalesced) */
    for (int e = t; e < HD*HD; e += 256) {
        int n = e >> 7, k = e & 127;
        Bs[n*C2_PH + k] = g_W16[e];
    }
    /* stage A: h1 = U+V -> bn1+lrelu -> fp16 */
    {
        int k = t & 127;
        for (int r = (t >> 7); r < 128; r += 2) {
            float v = g_U[uo[r] + k] + g_V[vo[r] + k];
            v = fmaf(sc[k], v, sh[k]);
            v = (v > 0.f) ? v : 0.2f*v;
            As[r*C2_PH + k] = __float2half(v);
        }
    }
    __syncthreads();

    /* mma mainloop: warp wid owns rows 16*wid..16*wid+15 */
    const uint32_t* As32 = (const uint32_t*)As;
    const uint32_t* Bs32 = (const uint32_t*)Bs;
    int gid = lane >> 2, tid = lane & 3;
    int ar0 = wid*16 + gid;
    float d[16][4];
#pragma unroll
    for (int nb = 0; nb < 16; nb++)
#pragma unroll
        for (int j = 0; j < 4; j++) d[nb][j] = 0.f;

#pragma unroll
    for (int k0 = 0; k0 < 8; k0++) {
        int kc = k0*8 + tid;
        uint32_t a0 = As32[ar0*C2_PW + kc];
        uint32_t a1 = As32[(ar0+8)*C2_PW + kc];
        uint32_t a2 = As32[ar0*C2_PW + kc + 4];
        uint32_t a3 = As32[(ar0+8)*C2_PW + kc + 4];
#pragma unroll
        for (int nb = 0; nb < 16; nb++) {
            uint32_t b0 = Bs32[(nb*8+gid)*C2_PW + kc];
            uint32_t b1 = Bs32[(nb*8+gid)*C2_PW + kc + 4];
            mma16816(d[nb], a0, a1, a2, a3, b0, b1);
        }
    }
    __syncthreads();

    /* epilogue tile in smem (half2, pitch 68 half2 per row) */
    __half2* hst2 = (__half2*)(smemraw + C2_AS);
#pragma unroll
    for (int nb = 0; nb < 16; nb++) {
        hst2[ar0*C2_PW + nb*4 + tid]     = __floats2half2_rn(d[nb][0], d[nb][1]);
        hst2[(ar0+8)*C2_PW + nb*4 + tid] = __floats2half2_rn(d[nb][2], d[nb][3]);
    }
    __syncthreads();
    /* coalesced global store (128 rows x 128 halfs) */
    {
        __half2* dst = (__half2*)&g_h2h[(size_t)rbase*HD];
        for (int e = t; e < 128*64; e += 256) {
            int r = e >> 6, j = e & 63;
            dst[e] = hst2[r*C2_PW + j];
        }
    }
    /* stats: 64 half2-cols x 4 rowgroups */
    {
        int c2 = t & 63, rg = t >> 6;
        float s0 = 0.f, q0 = 0.f, s1 = 0.f, q1 = 0.f;
        for (int r = rg*32; r < rg*32 + 32; r++) {
            float2 f = __half22float2(hst2[r*C2_PW + c2]);
            s0 += f.x; q0 += f.x*f.x;
            s1 += f.y; q1 += f.y*f.y;
        }
        atomicAdd(&g_sum[HD + 2*c2],     s0);
        atomicAdd(&g_sumsq[HD + 2*c2],   q0);
        atomicAdd(&g_sum[HD + 2*c2+1],   s1);
        atomicAdd(&g_sumsq[HD + 2*c2+1], q1);
    }
    __threadfence();
    if (t == 0) lastflag = (atomicAdd(&g_cnt[1], 1) == (int)gridDim.x - 1);
    __syncthreads();
    if (lastflag) bn_finalize(1, 128, invN, bn2g, bn2b, t);
}

/* ---------------- K5: conv3 GEMM (f32x2) + fused pool + finalize layer 2 ---- */
__global__ void __launch_bounds__(192) k_conv3p(const float* __restrict__ w3,
                                                const float* __restrict__ bn3g,
                                                const float* __restrict__ bn3b,
                                                float invN) {
    extern __shared__ char smemraw[];
    float* a_s = (float*)smemraw;          /* 160*130 */
    ull*   wp  = (ull*)(a_s + 160*130);    /* 64*24 u64 */
    float* sc  = (float*)(wp + 64*24);
    float* sh  = sc + 128;
    float* red = sh + 128;
    __shared__ int lastflag;

    int t = threadIdx.x, blk = blockIdx.x;
    int rbase = blk * 160;
    for (int e = t; e < 64*24; e += 192) {
        int pp = e / 24, col = e % 24;
        wp[e] = pack2(__ldg(&w3[(2*pp)*24 + col]), __ldg(&w3[(2*pp+1)*24 + col]));
    }
    if (t < 128) { sc[t] = g_scale[HD + t]; sh[t] = g_shift[HD + t]; }
    if (t < 48)  red[t] = 0.f;
    __syncthreads();

    const __half2* hp = (const __half2*)g_h2h + (size_t)rbase*64;
    for (int e = t; e < 160*64; e += 192) {
        int r = e >> 6, kp = e & 63;
        float2 f = __half22float2(hp[(size_t)r*64 + kp]);
        int k0 = 2*kp;
        float v0 = fmaf(sc[k0],   f.x, sh[k0]);   v0 = (v0 > 0.f) ? v0 : 0.2f*v0;
        float v1 = fmaf(sc[k0+1], f.y, sh[k0+1]); v1 = (v1 > 0.f) ? v1 : 0.2f*v1;
        a_s[r*130 + k0]     = v0;
        a_s[r*130 + k0 + 1] = v1;
    }
    __syncthreads();

    int col = t % 24, rg = t / 24;
    ull acc2[20];
#pragma unroll
    for (int r = 0; r < 20; r++) acc2[r] = 0ULL;
#pragma unroll 2
    for (int p = 0; p < 64; p++) {
        ull wv = wp[p*24 + col];
#pragma unroll
        for (int r = 0; r < 20; r++) {
            ull a = *(const ull*)&a_s[(r*8 + rg)*130 + 2*p];
            acc2[r] = ffma2(a, wv, acc2[r]);
        }
    }
    __syncthreads();
    float* h3s = a_s;
    float s = 0.f, s2 = 0.f;
#pragma unroll
    for (int r = 0; r < 20; r++) {
        float2 f = unpack2(acc2[r]);
        float v = f.x + f.y;
        h3s[(r*8 + rg)*24 + col] = v;
        s += v; s2 += v*v;
    }
    atomicAdd(&red[col], s);
    atomicAdd(&red[24 + col], s2);
    __syncthreads();

    {
        int pl = t / 24, c2 = t % 24;
        float mx = -3.4e38f, mn = 3.4e38f;
#pragma unroll
        for (int kk = 0; kk < KNN; kk++) {
            float v = h3s[(pl*KNN + kk)*24 + c2];
            mx = fmaxf(mx, v); mn = fminf(mn, v);
        }
        int pt = blk*8 + pl;
        g_pmax[pt*24 + c2] = mx;
        g_pmin[pt*24 + c2] = mn;
    }
    if (t < 24) {
        atomicAdd(&g_sum[2*HD + t],   red[t]);
        atomicAdd(&g_sumsq[2*HD + t], red[24 + t]);
    }
    __threadfence();
    if (t == 0) lastflag = (atomicAdd(&g_cnt[2], 1) == (int)gridDim.x - 1);
    __syncthreads();
    if (lastflag) bn_finalize(2, 24, invN, bn3g, bn3b, t);
}

/* ---------------- K6: ResNet-FC head (f32x2) ---------------- */
__global__ void __launch_bounds__(256) k_head(const float* __restrict__ p,
                       const float* __restrict__ fpw, const float* __restrict__ fpb,
                       const float* __restrict__ fcw, const float* __restrict__ fcb,
                       const float* __restrict__ b0w, const float* __restrict__ b0b,
                       const float* __restrict__ b1w, const float* __restrict__ b1b,
                       const float* __restrict__ fow, const float* __restrict__ fob,
                       float* __restrict__ out) {
    extern __shared__ char smemraw[];
    float* net  = (float*)smemraw;
    float* rnet = net  + 64*128;
    float* rhh  = rnet + 64*128;
    float* cb   = rhh  + 64*128;
    float* pb   = cb   + 64*24;
    float* fo   = pb   + 192;

    int t = threadIdx.x;
    int base = blockIdx.x * 64;
    for (int e = t; e < 64*CD; e += 256) {
        int c2 = e % 24;
        float scv = g_scale[2*HD + c2], shv = g_shift[2*HD + c2];
        float v = (scv >= 0.f) ? g_pmax[base*24 + e] : g_pmin[base*24 + e];
        v = fmaf(scv, v, shv);
        cb[e] = (v > 0.f) ? v : 0.2f*v;
    }
    if (t < 192) pb[t] = p[base*3 + t];
    if (t < 128) fo[t] = fow[t];
    __syncthreads();

    int cg  = (t & 31) * 4;
    int row0 = (t >> 5) * 8;

    {
        float4 w0 = *(const float4*)&fpw[0*HD + cg];
        float4 w1 = *(const float4*)&fpw[1*HD + cg];
        float4 w2 = *(const float4*)&fpw[2*HD + cg];
        float4 b4 = *(const float4*)&fpb[cg];
#pragma unroll
        for (int rr = 0; rr < 8; rr++) {
            int row = row0 + rr;
            float p0 = pb[row*3+0], p1 = pb[row*3+1], p2 = pb[row*3+2];
            float4 v;
            v.x = fmaf(p0,w0.x, fmaf(p1,w1.x, fmaf(p2,w2.x, b4.x)));
            v.y = fmaf(p0,w0.y, fmaf(p1,w1.y, fmaf(p2,w2.y, b4.y)));
            v.z = fmaf(p0,w0.z, fmaf(p1,w1.z, fmaf(p2,w2.z, b4.z)));
            v.w = fmaf(p0,w0.w, fmaf(p1,w1.w, fmaf(p2,w2.w, b4.w)));
            *(float4*)&net[row*128 + cg] = v;
        }
    }
    __syncthreads();

    for (int i = 0; i < NB; i++) {
        {
            float4 b4 = *(const float4*)&fcb[i*HD + cg];
            ull acc2[8][4];
#pragma unroll
            for (int rr = 0; rr < 8; rr++) {
                float4 v = *(const float4*)&net[(row0+rr)*128 + cg];
                acc2[rr][0] = pack2(v.x + b4.x, 0.f);
                acc2[rr][1] = pack2(v.y + b4.y, 0.f);
                acc2[rr][2] = pack2(v.z + b4.z, 0.f);
                acc2[rr][3] = pack2(v.w + b4.w, 0.f);
            }
#pragma unroll 2
            for (int k = 0; k < CD; k += 2) {
                float4 wa = __ldg((const float4*)&fcw[(i*CD + k)*HD + cg]);
                float4 wb = __ldg((const float4*)&fcw[(i*CD + k + 1)*HD + cg]);
                ull wx = pack2(wa.x, wb.x), wy = pack2(wa.y, wb.y);
                ull wz = pack2(wa.z, wb.z), ww = pack2(wa.w, wb.w);
#pragma unroll
                for (int rr = 0; rr < 8; rr++) {
                    ull a = *(const ull*)&cb[(row0+rr)*24 + k];
                    acc2[rr][0] = ffma2(a, wx, acc2[rr][0]);
                    acc2[rr][1] = ffma2(a, wy, acc2[rr][1]);
                    acc2[rr][2] = ffma2(a, wz, acc2[rr][2]);
                    acc2[rr][3] = ffma2(a, ww, acc2[rr][3]);
                }
            }
#pragma unroll
            for (int rr = 0; rr < 8; rr++) {
                int row = row0 + rr;
                float2 f0 = unpack2(acc2[rr][0]), f1 = unpack2(acc2[rr][1]);
                float2 f2 = unpack2(acc2[rr][2]), f3 = unpack2(acc2[rr][3]);
                float4 v; v.x = f0.x+f0.y; v.y = f1.x+f1.y; v.z = f2.x+f2.y; v.w = f3.x+f3.y;
                *(float4*)&net[row*128 + cg] = v;
                float4 rv;
                rv.x = fmaxf(v.x, 0.f); rv.y = fmaxf(v.y, 0.f);
                rv.z = fmaxf(v.z, 0.f); rv.w = fmaxf(v.w, 0.f);
                *(float4*)&rnet[row*128 + cg] = rv;
            }
        }
        __syncthreads();
        {
            float4 b4 = *(const float4*)&b0b[i*HD + cg];
            ull acc2[8][4];
#pragma unroll
            for (int rr = 0; rr < 8; rr++) {
                acc2[rr][0] = pack2(b4.x, 0.f); acc2[rr][1] = pack2(b4.y, 0.f);
                acc2[rr][2] = pack2(b4.z, 0.f); acc2[rr][3] = pack2(b4.w, 0.f);
            }
            const float* wbase = b0w + (size_t)i*HD*HD;
#pragma unroll 2
            for (int k = 0; k < HD; k += 2) {
                float4 wa = __ldg((const float4*)&wbase[k*HD + cg]);
                float4 wb = __ldg((const float4*)&wbase[(k+1)*HD + cg]);
                ull wx = pack2(wa.x, wb.x), wy = pack2(wa.y, wb.y);
                ull wz = pack2(wa.z, wb.z), ww = pack2(wa.w, wb.w);
#pragma unroll
                for (int rr = 0; rr < 8; rr++) {
                    ull a = *(const ull*)&rnet[(row0+rr)*128 + k];
                    acc2[rr][0] = ffma2(a, wx, acc2[rr][0]);
                    acc2[rr][1] = ffma2(a, wy, acc2[rr][1]);
                    acc2[rr][2] = ffma2(a, wz, acc2[rr][2]);
                    acc2[rr][3] = ffma2(a, ww, acc2[rr][3]);
                }
            }
#pragma unroll
            for (int rr = 0; rr < 8; rr++) {
                float2 f0 = unpack2(acc2[rr][0]), f1 = unpack2(acc2[rr][1]);
                float2 f2 = unpack2(acc2[rr][2]), f3 = unpack2(acc2[rr][3]);
                float4 rv;
                rv.x = fmaxf(f0.x+f0.y, 0.f); rv.y = fmaxf(f1.x+f1.y, 0.f);
                rv.z = fmaxf(f2.x+f2.y, 0.f); rv.w = fmaxf(f3.x+f3.y, 0.f);
                *(float4*)&rhh[(row0+rr)*128 + cg] = rv;
            }
        }
        __syncthreads();
        {
            float4 b4 = *(const float4*)&b1b[i*HD + cg];
            ull acc2[8][4];
#pragma unroll
            for (int rr = 0; rr < 8; rr++) {
                acc2[rr][0] = pack2(b4.x, 0.f); acc2[rr][1] = pack2(b4.y, 0.f);
                acc2[rr][2] = pack2(b4.z, 0.f); acc2[rr][3] = pack2(b4.w, 0.f);
            }
            const float* wbase = b1w + (size_t)i*HD*HD;
#pragma unroll 2
            for (int k = 0; k < HD; k += 2) {
                float4 wa = __ldg((const float4*)&wbase[k*HD + cg]);
                float4 wb = __ldg((const float4*)&wbase[(k+1)*HD + cg]);
                ull wx = pack2(wa.x, wb.x), wy = pack2(wa.y, wb.y);
                ull wz = pack2(wa.z, wb.z), ww = pack2(wa.w, wb.w);
#pragma unroll
                for (int rr = 0; rr < 8; rr++) {
                    ull a = *(const ull*)&rhh[(row0+rr)*128 + k];
                    acc2[rr][0] = ffma2(a, wx, acc2[rr][0]);
                    acc2[rr][1] = ffma2(a, wy, acc2[rr][1]);
                    acc2[rr][2] = ffma2(a, wz, acc2[rr][2]);
                    acc2[rr][3] = ffma2(a, ww, acc2[rr][3]);
                }
            }
#pragma unroll
            for (int rr = 0; rr < 8; rr++) {
                int row = row0 + rr;
                float2 f0 = unpack2(acc2[rr][0]), f1 = unpack2(acc2[rr][1]);
                float2 f2 = unpack2(acc2[rr][2]), f3 = unpack2(acc2[rr][3]);
                float4 v = *(const float4*)&net[row*128 + cg];
                v.x += f0.x+f0.y; v.y += f1.x+f1.y;
                v.z += f2.x+f2.y; v.w += f3.x+f3.y;
                *(float4*)&net[row*128 + cg] = v;
            }
        }
        __syncthreads();
    }

    if (t < 64) {
        float s = fob[0];
        for (int c2 = 0; c2 < HD; c2++)
            s = fmaf(fmaxf(net[t*128 + c2], 0.f), fo[c2], s);
        out[base + t] = s;
    }
}

/* ---------------- launch ---------------- */
extern "C" void kernel_launch(void* const* d_in, const int* in_sizes, int n_in,
                              void* d_out, int out_size) {
    (void)in_sizes; (void)n_in; (void)out_size;
    const float* p     = (const float*)d_in[0];
    const float* pc    = (const float*)d_in[1];
    const float* feat  = (const float*)d_in[2];
    const float* w1    = (const float*)d_in[3];
    const float* bn1g  = (const float*)d_in[4];
    const float* bn1b  = (const float*)d_in[5];
    const float* w2    = (const float*)d_in[6];
    const float* bn2g  = (const float*)d_in[7];
    const float* bn2b  = (const float*)d_in[8];
    const float* w3    = (const float*)d_in[9];
    const float* bn3g  = (const float*)d_in[10];
    const float* bn3b  = (const float*)d_in[11];
    const float* fpw   = (const float*)d_in[12];
    const float* fpb   = (const float*)d_in[13];
    const float* fcw   = (const float*)d_in[14];
    const float* fcb   = (const float*)d_in[15];
    const float* b0w   = (const float*)d_in[16];
    const float* b0b   = (const float*)d_in[17];
    const float* b1w   = (const float*)d_in[18];
    const float* b1b   = (const float*)d_in[19];
    const float* fow   = (const float*)d_in[20];
    const float* fob   = (const float*)d_in[21];
    float* out = (float*)d_out;

    const int SMEM2 = C2_SMEM;                                        /* ~71.7KB */
    const int SMEM3 = 160*130*4 + 64*24*8 + 2*128*4 + 48*4;           /* ~96.7KB */
    const int SMEMH = (3*64*128 + 64*24 + 192 + 128) * 4;             /* ~105.7KB*/
    cudaFuncSetAttribute(k_conv2,  cudaFuncAttributeMaxDynamicSharedMemorySize, SMEM2);
    cudaFuncSetAttribute(k_conv3p, cudaFuncAttributeMaxDynamicSharedMemorySize, SMEM3);
    cudaFuncSetAttribute(k_head,   cudaFuncAttributeMaxDynamicSharedMemorySize, SMEMH);

    float invN = 1.0f / (float)NROWS;

    k_knn<<<dim3(NX/256, BSZ), 256>>>(p, pc);
    k_preUV<<<128 + NPTS/64, 128>>>(p, pc, feat, w1);
    k_prepW<<<HD*HD/256, 256>>>(w2);
    k_stats1<<<NROWS/512, 256>>>(bn1g, bn1b, invN);
    k_conv2<<<NROWS/128, 256, SMEM2>>>(bn2g, bn2b, invN);
    k_conv3p<<<NROWS/160, 192, SMEM3>>>(w3, bn3g, bn3b, invN);
    k_head<<<NPTS/64, 256, SMEMH>>>(p, fpw, fpb, fcw, fcb,
                                    b0w, b0b, b1w, b1b, fow, fob, out);
}